// round 12
// baseline (speedup 1.0000x reference)
#include <cuda_runtime.h>
#include <cuda_fp16.h>
#include <cstdint>

#define EMBED   768
#define THREE_E 2304
#define HEADS   12
#define HDIM    64
#define SEQ     1024
#define BATCH   8
#define TOKENS  (BATCH*SEQ)

// QKV scratch: [8192 tokens][2304] fp32 (q | k | v, each 768 = 12 heads * 64)
__device__ float g_qkv[(size_t)TOKENS * THREE_E];

// ---------- packed f32x2 helpers (sm_100+) ----------
__device__ __forceinline__ unsigned long long dup2(float x){
    unsigned long long r;
    asm("mov.b64 %0, {%1, %1};" : "=l"(r) : "f"(x));
    return r;
}
__device__ __forceinline__ float2 up2(unsigned long long v){
    float2 r;
    asm("mov.b64 {%0, %1}, %2;" : "=f"(r.x), "=f"(r.y) : "l"(v));
    return r;
}
__device__ __forceinline__ void fma2(unsigned long long &d, unsigned long long a, unsigned long long b){
    asm("fma.rn.f32x2 %0, %1, %2, %0;" : "+l"(d) : "l"(a), "l"(b));
}

// ---------- mma helpers ----------
__device__ __forceinline__ float tf32r(float x){
    uint32_t u;
    asm("cvt.rna.tf32.f32 %0, %1;" : "=r"(u) : "f"(x));
    return __uint_as_float(u);
}
__device__ __forceinline__ void mma_tf32(float c[4], const uint32_t a[4], const uint32_t b[2]){
    asm volatile(
        "mma.sync.aligned.m16n8k8.row.col.f32.tf32.tf32.f32 "
        "{%0,%1,%2,%3}, {%4,%5,%6,%7}, {%8,%9}, {%0,%1,%2,%3};"
        : "+f"(c[0]), "+f"(c[1]), "+f"(c[2]), "+f"(c[3])
        : "r"(a[0]), "r"(a[1]), "r"(a[2]), "r"(a[3]), "r"(b[0]), "r"(b[1]));
}

// ============================================================
// Kernel 1: QKV GEMM (scalar f32x2 — known good, exact fp32).
// row0 parameter selects the token-row half (0 or 4096).
// ============================================================
__global__ __launch_bounds__(256, 2)
void qkv_gemm(const float* __restrict__ X, const float* __restrict__ W,
              const float* __restrict__ bias, int rowbase){
    __shared__ float As[16][128];
    __shared__ float Bs[16][128];

    const int tid = threadIdx.x;
    const int bm = rowbase + blockIdx.y * 128;
    const int bn = blockIdx.x * 128;
    const int tx = tid & 15;
    const int ty = tid >> 4;
    const int lr = tid >> 2;
    const int lc = (tid & 3) << 2;

    unsigned long long acc[8][4];
    #pragma unroll
    for (int i = 0; i < 8; i++)
        #pragma unroll
        for (int j = 0; j < 4; j++) acc[i][j] = 0ull;

    const float* Ap0 = X + (size_t)(bm + lr)      * EMBED + lc;
    const float* Ap1 = X + (size_t)(bm + lr + 64) * EMBED + lc;
    const float* Bp0 = W + (size_t)(bn + lr)      * EMBED + lc;
    const float* Bp1 = W + (size_t)(bn + lr + 64) * EMBED + lc;

    float4 pa0 = *(const float4*)Ap0;
    float4 pa1 = *(const float4*)Ap1;
    float4 pb0 = *(const float4*)Bp0;
    float4 pb1 = *(const float4*)Bp1;

    const int NKT = EMBED / 16;
    for (int kt = 0; kt < NKT; kt++){
        __syncthreads();
        {
            float a0[4] = {pa0.x, pa0.y, pa0.z, pa0.w};
            float a1[4] = {pa1.x, pa1.y, pa1.z, pa1.w};
            float b0[4] = {pb0.x, pb0.y, pb0.z, pb0.w};
            float b1[4] = {pb1.x, pb1.y, pb1.z, pb1.w};
            #pragma unroll
            for (int i = 0; i < 4; i++){
                As[lc + i][lr]      = a0[i];
                As[lc + i][lr + 64] = a1[i];
                Bs[lc + i][lr]      = b0[i];
                Bs[lc + i][lr + 64] = b1[i];
            }
        }
        __syncthreads();
        if (kt + 1 < NKT){
            pa0 = *(const float4*)(Ap0 + (kt + 1) * 16);
            pa1 = *(const float4*)(Ap1 + (kt + 1) * 16);
            pb0 = *(const float4*)(Bp0 + (kt + 1) * 16);
            pb1 = *(const float4*)(Bp1 + (kt + 1) * 16);
        }
        #pragma unroll
        for (int kk = 0; kk < 16; kk++){
            float4 a0 = *(const float4*)&As[kk][ty * 8];
            float4 a1 = *(const float4*)&As[kk][ty * 8 + 4];
            ulonglong2 b0 = *(const ulonglong2*)&Bs[kk][tx * 8];
            ulonglong2 b1 = *(const ulonglong2*)&Bs[kk][tx * 8 + 4];
            float av[8] = {a0.x, a0.y, a0.z, a0.w, a1.x, a1.y, a1.z, a1.w};
            #pragma unroll
            for (int i = 0; i < 8; i++){
                unsigned long long aa = dup2(av[i]);
                fma2(acc[i][0], aa, b0.x);
                fma2(acc[i][1], aa, b0.y);
                fma2(acc[i][2], aa, b1.x);
                fma2(acc[i][3], aa, b1.y);
            }
        }
    }

    float4 bs0 = *(const float4*)&bias[bn + tx * 8];
    float4 bs1 = *(const float4*)&bias[bn + tx * 8 + 4];
    #pragma unroll
    for (int i = 0; i < 8; i++){
        float2 c0 = up2(acc[i][0]), c1 = up2(acc[i][1]);
        float2 c2 = up2(acc[i][2]), c3 = up2(acc[i][3]);
        float4 o0 = make_float4(c0.x + bs0.x, c0.y + bs0.y, c1.x + bs0.z, c1.y + bs0.w);
        float4 o1 = make_float4(c2.x + bs1.x, c2.y + bs1.y, c3.x + bs1.z, c3.y + bs1.w);
        float* cp = g_qkv + (size_t)(bm + ty * 8 + i) * THREE_E + bn + tx * 8;
        *(float4*)cp       = o0;
        *(float4*)(cp + 4) = o1;
    }
}

// ============================================================
// Kernel 2: fused attention (byte-identical math to R11).
// bh0 parameter selects the (batch*head) half (0 or 48).
// ============================================================
#define SSTR2 1034
#define QSTR  68
#define KSTR  68
#define VSTR  68
#define SS_BYTES  (32 * SSTR2 * 2)
#define K_BYTES   (128 * KSTR * 4)
#define ATTN_SMEM (SS_BYTES + K_BYTES + 128 + 32 * QSTR * 4)   // 109824

__global__ __launch_bounds__(256, 2)
void attn_kernel(float* __restrict__ out, int bh0){
    extern __shared__ char smraw[];
    __half* Ss  = (__half*)smraw;
    float* Ks   = (float*)(smraw + SS_BYTES);
    float* rinv = (float*)(smraw + SS_BYTES + K_BYTES);
    float* Qs   = rinv + 32;
    float* Vs0  = Ks;
    float* Vs1  = Ks + 64 * VSTR;

    const int tid  = threadIdx.x;
    const int warp = tid >> 5;
    const int lane = tid & 31;
    const int bh   = bh0 + (blockIdx.x >> 5);
    const int row0 = (blockIdx.x & 31) * 32;
    const int b = bh / HEADS;
    const int h = bh % HEADS;

    const float* qbase = g_qkv + (size_t)(b * SEQ) * THREE_E + h * HDIM;
    const float* kbase = qbase + EMBED;
    const float* vbase = qbase + 2 * EMBED;

    // ---- load Q block 32x64 ----
    #pragma unroll
    for (int it = 0; it < 2; it++){
        int idx = it * 256 + tid;
        int dc = idx & 15, r = idx >> 4;
        float4 v = *(const float4*)(qbase + (size_t)(row0 + r) * THREE_E + dc * 4);
        *(float4*)&Qs[r * QSTR + dc * 4] = v;
    }
    __syncthreads();

    // =========== pass 1: S = floor(Q K^T / 8), exact fp32 ===========
    const int r0 = warp * 4;

    #pragma unroll 1
    for (int kt = 0; kt < SEQ / 128; kt++){
        if (kt) __syncthreads();
        #pragma unroll
        for (int it = 0; it < 8; it++){
            int idx = it * 256 + tid;
            int m = idx >> 4, dc = idx & 15;
            float4 v = *(const float4*)(kbase + (size_t)(kt * 128 + m) * THREE_E + dc * 4);
            *(float4*)&Ks[m * KSTR + dc * 4] = v;
        }
        __syncthreads();

        unsigned long long acc[4][4];
        #pragma unroll
        for (int r = 0; r < 4; r++)
            #pragma unroll
            for (int i = 0; i < 4; i++) acc[r][i] = 0ull;

        #pragma unroll
        for (int dg = 0; dg < 16; dg++){
            ulonglong2 q[4];
            #pragma unroll
            for (int r = 0; r < 4; r++)
                q[r] = *(const ulonglong2*)&Qs[(r0 + r) * QSTR + dg * 4];
            #pragma unroll
            for (int i = 0; i < 4; i++){
                ulonglong2 kv = *(const ulonglong2*)&Ks[(lane + 32 * i) * KSTR + dg * 4];
                #pragma unroll
                for (int r = 0; r < 4; r++){
                    fma2(acc[r][i], q[r].x, kv.x);
                    fma2(acc[r][i], q[r].y, kv.y);
                }
            }
        }

        #pragma unroll
        for (int r = 0; r < 4; r++){
            __half* srow = Ss + (r0 + r) * SSTR2 + kt * 128 + lane;
            #pragma unroll
            for (int i = 0; i < 4; i++){
                float2 t = up2(acc[r][i]);
                srow[32 * i] = __float2half_rn(floorf((t.x + t.y) * 0.125f));
            }
        }
    }
    __syncthreads();

    // ---- prefetch V tile 0 ----
    float4 vp[4];
    #pragma unroll
    for (int it = 0; it < 4; it++){
        int idx = it * 256 + tid;
        int m = idx >> 4, dc = idx & 15;
        vp[it] = *(const float4*)(vbase + (size_t)m * THREE_E + dc * 4);
    }

    // =========== softmax (fp16 strip; sum from quantized weights) ===========
    #pragma unroll
    for (int rr = 0; rr < 4; rr++){
        int r = warp * 4 + rr;
        __half2* row2 = (__half2*)(Ss + r * SSTR2);
        float mx = -1e30f;
        #pragma unroll
        for (int i = 0; i < 16; i++){
            float2 f = __half22float2(row2[lane + i * 32]);
            mx = fmaxf(mx, fmaxf(f.x, f.y));
        }
        #pragma unroll
        for (int o = 16; o > 0; o >>= 1) mx = fmaxf(mx, __shfl_xor_sync(0xffffffffu, mx, o));
        float sum = 0.f;
        #pragma unroll
        for (int i = 0; i < 16; i++){
            float2 f = __half22float2(row2[lane + i * 32]);
            __half2 e2 = __floats2half2_rn(__expf(f.x - mx), __expf(f.y - mx));
            row2[lane + i * 32] = e2;
            float2 q = __half22float2(e2);
            sum += q.x + q.y;
        }
        #pragma unroll
        for (int o = 16; o > 0; o >>= 1) sum += __shfl_xor_sync(0xffffffffu, sum, o);
        if (lane == 0) rinv[r] = 1.0f / sum;
    }

    // ---- prime pass 2 ----
    #pragma unroll
    for (int it = 0; it < 4; it++){
        int idx = it * 256 + tid;
        int m = idx >> 4, dc = idx & 15;
        float4 v = vp[it];
        v.x = tf32r(v.x); v.y = tf32r(v.y); v.z = tf32r(v.z); v.w = tf32r(v.w);
        *(float4*)&Vs0[m * VSTR + dc * 4] = v;
    }
    #pragma unroll
    for (int it = 0; it < 4; it++){
        int idx = it * 256 + tid;
        int m = idx >> 4, dc = idx & 15;
        vp[it] = *(const float4*)(vbase + (size_t)(64 + m) * THREE_E + dc * 4);
    }
    __syncthreads();

    // =========== pass 2: C = E @ V via tf32 mma (double-buffered V) ===========
    const int mtile = warp & 1;
    const int nt0   = (warp >> 1) * 2;
    float C0[4] = {0.f,0.f,0.f,0.f}, C1[4] = {0.f,0.f,0.f,0.f};

    const __half* eA0 = Ss + (mtile * 16 + (lane >> 2)) * SSTR2 + (lane & 3);
    const __half* eA1 = eA0 + 8 * SSTR2;
    const int bm_ = lane & 3;
    const int bd_ = lane >> 2;
    const int v_off = bm_ * VSTR + nt0 * 8 + bd_;

    #pragma unroll 1
    for (int kt = 0; kt < 16; kt++){
        const float* cur = (kt & 1) ? Vs1 : Vs0;
        const float* vs_b0 = cur + v_off;

        #pragma unroll
        for (int ks = 0; ks < 8; ks++){
            const int eo = kt * 64 + ks * 8;
            uint32_t ea[4];
            ea[0] = __float_as_uint(__half2float(eA0[eo]));
            ea[1] = __float_as_uint(__half2float(eA1[eo]));
            ea[2] = __float_as_uint(__half2float(eA0[eo + 4]));
            ea[3] = __float_as_uint(__half2float(eA1[eo + 4]));
            const float* vrow0 = vs_b0 + (8 * ks) * VSTR;
            const float* vrow1 = vrow0 + 4 * VSTR;
            uint32_t b0[2], b1[2];
            b0[0] = __float_as_uint(vrow0[0]);
            b0[1] = __float_as_uint(vrow1[0]);
            b1[0] = __float_as_uint(vrow0[8]);
            b1[1] = __float_as_uint(vrow1[8]);
            mma_tf32(C0, ea, b0);
            mma_tf32(C1, ea, b1);
        }

        if (kt < 15){
            float* nxt = (kt & 1) ? Vs0 : Vs1;
            #pragma unroll
            for (int it = 0; it < 4; it++){
                int idx = it * 256 + tid;
                int m = idx >> 4, dc = idx & 15;
                float4 v = vp[it];
                v.x = tf32r(v.x); v.y = tf32r(v.y); v.z = tf32r(v.z); v.w = tf32r(v.w);
                *(float4*)&nxt[m * VSTR + dc * 4] = v;
            }
            if (kt < 14){
                #pragma unroll
                for (int it = 0; it < 4; it++){
                    int idx = it * 256 + tid;
                    int m = idx >> 4, dc = idx & 15;
                    vp[it] = *(const float4*)(vbase + (size_t)((kt + 2) * 64 + m) * THREE_E + dc * 4);
                }
            }
        }
        __syncthreads();
    }

    // ---- epilogue ----
    {
        const int er0 = mtile * 16 + (lane >> 2);
        const int d0  = nt0 * 8 + 2 * (lane & 3);
        float i0 = rinv[er0], i1 = rinv[er0 + 8];
        float* op0 = out + (size_t)(bh * SEQ + row0 + er0) * HDIM + d0;
        float* op1 = op0 + 8 * HDIM;
        *(float2*)op0       = make_float2(C0[0] * i0, C0[1] * i0);
        *(float2*)(op0 + 8) = make_float2(C1[0] * i0, C1[1] * i0);
        *(float2*)op1       = make_float2(C0[2] * i1, C0[3] * i1);
        *(float2*)(op1 + 8) = make_float2(C1[2] * i1, C1[3] * i1);
    }
}

// ============================================================
// launch: half-split pipeline with fork/join onto a 2nd stream.
//   s0: G(batches 0-3) -> G(batches 4-7)
//   s2:        A(0-3, after ev0)  ||  A(4-7, after ev1)
// Streams/events are created once, on the first (correctness,
// pre-capture) call; no device memory involved. The event
// fork/join is the standard graph-capture-legal pattern.
// ============================================================
extern "C" void kernel_launch(void* const* d_in, const int* in_sizes, int n_in,
                              void* d_out, int out_size) {
    const float* x    = (const float*)d_in[0];   // [8,1024,768]
    const float* Wqkv = (const float*)d_in[1];   // [2304,768]
    const float* bqkv = (const float*)d_in[2];   // [2304]
    float* out = (float*)d_out;                  // [8,12,1024,64]

    static cudaStream_t s2 = nullptr;
    static cudaEvent_t ev0 = nullptr, ev1 = nullptr, evJ = nullptr;
    if (s2 == nullptr){
        cudaStreamCreateWithFlags(&s2, cudaStreamNonBlocking);
        cudaEventCreateWithFlags(&ev0, cudaEventDisableTiming);
        cudaEventCreateWithFlags(&ev1, cudaEventDisableTiming);
        cudaEventCreateWithFlags(&evJ, cudaEventDisableTiming);
        cudaFuncSetAttribute(attn_kernel, cudaFuncAttributeMaxDynamicSharedMemorySize, ATTN_SMEM);
    }

    const dim3 ggemm(THREE_E / 128, 32);   // half the token rows per launch

    // half 0 GEMM (token rows 0..4095)
    qkv_gemm<<<ggemm, 256>>>(x, Wqkv, bqkv, 0);
    cudaEventRecord(ev0, 0);

    // half 1 GEMM (token rows 4096..8191) — overlaps attn half 0 on s2
    qkv_gemm<<<ggemm, 256>>>(x, Wqkv, bqkv, 4096);
    cudaEventRecord(ev1, 0);

    // attn half 0 (bh 0..47) on s2, gated on ev0
    cudaStreamWaitEvent(s2, ev0, 0);
    attn_kernel<<<48 * 32, 256, ATTN_SMEM, s2>>>(out, 0);

    // attn half 1 (bh 48..95) on s2, gated on ev1 (and stream order after A0)
    cudaStreamWaitEvent(s2, ev1, 0);
    attn_kernel<<<48 * 32, 256, ATTN_SMEM, s2>>>(out, 48);

    // join s2 back into the main stream
    cudaEventRecord(evJ, s2);
    cudaStreamWaitEvent(0, evJ, 0);
}

// round 13
// speedup vs baseline: 1.1148x; 1.1148x over previous
#include <cuda_runtime.h>
#include <cuda_fp16.h>
#include <cstdint>

#define EMBED   768
#define THREE_E 2304
#define HEADS   12
#define HDIM    64
#define SEQ     1024
#define BATCH   8
#define TOKENS  (BATCH*SEQ)

// QKV scratch: [8192 tokens][2304] fp32 (q | k | v, each 768 = 12 heads * 64)
__device__ float g_qkv[(size_t)TOKENS * THREE_E];

// ---------- packed f32x2 helpers (sm_100+) ----------
__device__ __forceinline__ unsigned long long dup2(float x){
    unsigned long long r;
    asm("mov.b64 %0, {%1, %1};" : "=l"(r) : "f"(x));
    return r;
}
__device__ __forceinline__ float2 up2(unsigned long long v){
    float2 r;
    asm("mov.b64 {%0, %1}, %2;" : "=f"(r.x), "=f"(r.y) : "l"(v));
    return r;
}
__device__ __forceinline__ void fma2(unsigned long long &d, unsigned long long a, unsigned long long b){
    asm("fma.rn.f32x2 %0, %1, %2, %0;" : "+l"(d) : "l"(a), "l"(b));
}

// ---------- mma helpers ----------
__device__ __forceinline__ uint32_t smem_u32(const void* p){
    uint32_t a;
    asm("{ .reg .u64 t; cvta.to.shared.u64 t, %1; cvt.u32.u64 %0, t; }" : "=r"(a) : "l"(p));
    return a;
}
__device__ __forceinline__ float tf32r(float x){
    uint32_t u;
    asm("cvt.rna.tf32.f32 %0, %1;" : "=r"(u) : "f"(x));
    return __uint_as_float(u);
}
__device__ __forceinline__ void ldsm4(uint32_t r[4], uint32_t addr){
    asm volatile("ldmatrix.sync.aligned.m8n8.x4.shared.b16 {%0,%1,%2,%3}, [%4];"
                 : "=r"(r[0]), "=r"(r[1]), "=r"(r[2]), "=r"(r[3]) : "r"(addr));
}
__device__ __forceinline__ void ldsm2(uint32_t r[2], uint32_t addr){
    asm volatile("ldmatrix.sync.aligned.m8n8.x2.shared.b16 {%0,%1}, [%2];"
                 : "=r"(r[0]), "=r"(r[1]) : "r"(addr));
}
__device__ __forceinline__ void mma_tf32(float c[4], const uint32_t a[4], const uint32_t b[2]){
    asm volatile(
        "mma.sync.aligned.m16n8k8.row.col.f32.tf32.tf32.f32 "
        "{%0,%1,%2,%3}, {%4,%5,%6,%7}, {%8,%9}, {%0,%1,%2,%3};"
        : "+f"(c[0]), "+f"(c[1]), "+f"(c[2]), "+f"(c[3])
        : "r"(a[0]), "r"(a[1]), "r"(a[2]), "r"(a[3]), "r"(b[0]), "r"(b[1]));
}

// ============================================================
// Kernel 1a: Q/K GEMM — scalar f32x2, exact fp32.
// Covers output columns [0, 1536) only (grid.x = 12).
// ============================================================
__global__ __launch_bounds__(256, 2)
void qkv_gemm(const float* __restrict__ X, const float* __restrict__ W,
              const float* __restrict__ bias){
    __shared__ float As[16][128];
    __shared__ float Bs[16][128];

    const int tid = threadIdx.x;
    const int bm = blockIdx.y * 128;
    const int bn = blockIdx.x * 128;      // < 1536
    const int tx = tid & 15;
    const int ty = tid >> 4;
    const int lr = tid >> 2;
    const int lc = (tid & 3) << 2;

    unsigned long long acc[8][4];
    #pragma unroll
    for (int i = 0; i < 8; i++)
        #pragma unroll
        for (int j = 0; j < 4; j++) acc[i][j] = 0ull;

    const float* Ap0 = X + (size_t)(bm + lr)      * EMBED + lc;
    const float* Ap1 = X + (size_t)(bm + lr + 64) * EMBED + lc;
    const float* Bp0 = W + (size_t)(bn + lr)      * EMBED + lc;
    const float* Bp1 = W + (size_t)(bn + lr + 64) * EMBED + lc;

    float4 pa0 = *(const float4*)Ap0;
    float4 pa1 = *(const float4*)Ap1;
    float4 pb0 = *(const float4*)Bp0;
    float4 pb1 = *(const float4*)Bp1;

    const int NKT = EMBED / 16;
    for (int kt = 0; kt < NKT; kt++){
        __syncthreads();
        {
            float a0[4] = {pa0.x, pa0.y, pa0.z, pa0.w};
            float a1[4] = {pa1.x, pa1.y, pa1.z, pa1.w};
            float b0[4] = {pb0.x, pb0.y, pb0.z, pb0.w};
            float b1[4] = {pb1.x, pb1.y, pb1.z, pb1.w};
            #pragma unroll
            for (int i = 0; i < 4; i++){
                As[lc + i][lr]      = a0[i];
                As[lc + i][lr + 64] = a1[i];
                Bs[lc + i][lr]      = b0[i];
                Bs[lc + i][lr + 64] = b1[i];
            }
        }
        __syncthreads();
        if (kt + 1 < NKT){
            pa0 = *(const float4*)(Ap0 + (kt + 1) * 16);
            pa1 = *(const float4*)(Ap1 + (kt + 1) * 16);
            pb0 = *(const float4*)(Bp0 + (kt + 1) * 16);
            pb1 = *(const float4*)(Bp1 + (kt + 1) * 16);
        }
        #pragma unroll
        for (int kk = 0; kk < 16; kk++){
            float4 a0 = *(const float4*)&As[kk][ty * 8];
            float4 a1 = *(const float4*)&As[kk][ty * 8 + 4];
            ulonglong2 b0 = *(const ulonglong2*)&Bs[kk][tx * 8];
            ulonglong2 b1 = *(const ulonglong2*)&Bs[kk][tx * 8 + 4];
            float av[8] = {a0.x, a0.y, a0.z, a0.w, a1.x, a1.y, a1.z, a1.w};
            #pragma unroll
            for (int i = 0; i < 8; i++){
                unsigned long long aa = dup2(av[i]);
                fma2(acc[i][0], aa, b0.x);
                fma2(acc[i][1], aa, b0.y);
                fma2(acc[i][2], aa, b1.x);
                fma2(acc[i][3], aa, b1.y);
            }
        }
    }

    float4 bs0 = *(const float4*)&bias[bn + tx * 8];
    float4 bs1 = *(const float4*)&bias[bn + tx * 8 + 4];
    #pragma unroll
    for (int i = 0; i < 8; i++){
        float2 c0 = up2(acc[i][0]), c1 = up2(acc[i][1]);
        float2 c2 = up2(acc[i][2]), c3 = up2(acc[i][3]);
        float4 o0 = make_float4(c0.x + bs0.x, c0.y + bs0.y, c1.x + bs0.z, c1.y + bs0.w);
        float4 o1 = make_float4(c2.x + bs1.x, c2.y + bs1.y, c3.x + bs1.z, c3.y + bs1.w);
        float* cp = g_qkv + (size_t)(bm + ty * 8 + i) * THREE_E + bn + tx * 8;
        *(float4*)cp       = o0;
        *(float4*)(cp + 4) = o1;
    }
}

// ============================================================
// Kernel 1b: V GEMM — single-tf32 mma.sync (precision-tolerant path).
// Output columns [1536, 2304) (grid.x = 6). Same C^T = W X^T layout
// and ldmatrix addressing as the validated R5/R6 kernel, minus the
// hi/lo split (measured to contribute nothing).
// ============================================================
#define VBK    32
#define VNST   (EMBED / VBK)     // 24
#define VTILE  16384             // 128 rows x 32 f32
#define VSTAGE (2 * VTILE)       // Wt | Xt
#define VGEMM_SMEM 67584         // max(2*VSTAGE=65536, epilogue 128*132*4)

__global__ __launch_bounds__(256, 1)
void qkv_gemm_v(const float* __restrict__ X, const float* __restrict__ W,
                const float* __restrict__ bias){
    extern __shared__ char dyn[];
    const int tid  = threadIdx.x;
    const int warp = tid >> 5;
    const int lane = tid & 31;
    const int bn   = 1536 + blockIdx.x * 128;   // V columns
    const int bm   = blockIdx.y * 128;

    const uint32_t sbase = smem_u32(dyn);
    const int na0 = (warp >> 2) * 64;
    const int mb0 = (warp & 3) * 32;
    const int swz = lane & 7;

    const uint32_t a_row_b = (uint32_t)(na0 + (lane & 7) + ((lane >> 3) & 1) * 8) * 128;
    const uint32_t a_half  = (uint32_t)(lane >> 4);
    const uint32_t b_row_b = (uint32_t)(mb0 + (lane & 7)) * 128;
    const uint32_t b_half  = (uint32_t)((lane >> 3) & 1);

    float C[4][4][4];
    #pragma unroll
    for (int i = 0; i < 4; i++)
        #pragma unroll
        for (int j = 0; j < 4; j++)
            #pragma unroll
            for (int q = 0; q < 4; q++) C[i][j][q] = 0.f;

    const int lrm = tid >> 3;
    const int lc4 = tid & 7;

    float4 wv[4], xv[4];
    #pragma unroll
    for (int it = 0; it < 4; it++){
        int rm = lrm + it * 32;
        wv[it] = *(const float4*)(W + (size_t)(bn + rm) * EMBED + lc4 * 4);
        xv[it] = *(const float4*)(X + (size_t)(bm + rm) * EMBED + lc4 * 4);
    }

    #pragma unroll 1
    for (int s = 0; s < VNST; s++){
        const uint32_t bufb = (uint32_t)(s & 1) * VSTAGE;
        char* wt = dyn + bufb;
        char* xt = wt + VTILE;

        // ---- tf32-round + STS (swizzled row-major) ----
        #pragma unroll
        for (int it = 0; it < 4; it++){
            int rm = lrm + it * 32;
            uint32_t off = (uint32_t)rm * 128 + (uint32_t)((lc4 ^ (rm & 7)) << 4);
            float4 a = wv[it], b = xv[it];
            a.x = tf32r(a.x); a.y = tf32r(a.y); a.z = tf32r(a.z); a.w = tf32r(a.w);
            b.x = tf32r(b.x); b.y = tf32r(b.y); b.z = tf32r(b.z); b.w = tf32r(b.w);
            *(float4*)(wt + off) = a;
            *(float4*)(xt + off) = b;
        }
        __syncthreads();

        if (s + 1 < VNST){
            #pragma unroll
            for (int it = 0; it < 4; it++){
                int rm = lrm + it * 32;
                wv[it] = *(const float4*)(W + (size_t)(bn + rm) * EMBED + (s + 1) * VBK + lc4 * 4);
                xv[it] = *(const float4*)(X + (size_t)(bm + rm) * EMBED + (s + 1) * VBK + lc4 * 4);
            }
        }

        const uint32_t wA = sbase + bufb;
        const uint32_t xA = wA + VTILE;

        #pragma unroll
        for (int ks = 0; ks < 4; ks++){
            uint32_t ah[4][4], bh[4][2];
            const uint32_t ac = (uint32_t)(2 * ks) + a_half;
            const uint32_t bc = (uint32_t)(2 * ks) + b_half;
            #pragma unroll
            for (int at = 0; at < 4; at++)
                ldsm4(ah[at], wA + a_row_b + (uint32_t)at * 2048 + (uint32_t)((ac ^ swz) << 4));
            #pragma unroll
            for (int bt = 0; bt < 4; bt++)
                ldsm2(bh[bt], xA + b_row_b + (uint32_t)bt * 1024 + (uint32_t)((bc ^ swz) << 4));
            #pragma unroll
            for (int at = 0; at < 4; at++)
                #pragma unroll
                for (int bt = 0; bt < 4; bt++)
                    mma_tf32(C[at][bt], ah[at], bh[bt]);
        }
        __syncthreads();
    }

    // ---- epilogue: transpose via smem + bias -> g_qkv ----
    float* buf = (float*)dyn;    // 128 x 132
    #pragma unroll
    for (int at = 0; at < 4; at++){
        int n0 = na0 + at * 16 + (lane >> 2);
        #pragma unroll
        for (int bt = 0; bt < 4; bt++){
            int m0 = mb0 + bt * 8 + 2 * (lane & 3);
            buf[(m0    ) * 132 + n0    ] = C[at][bt][0];
            buf[(m0 + 1) * 132 + n0    ] = C[at][bt][1];
            buf[(m0    ) * 132 + n0 + 8] = C[at][bt][2];
            buf[(m0 + 1) * 132 + n0 + 8] = C[at][bt][3];
        }
    }
    __syncthreads();
    #pragma unroll
    for (int it = 0; it < 16; it++){
        int idx = it * 256 + tid;
        int m = idx >> 5, c4 = idx & 31;
        float4 v  = *(float4*)&buf[m * 132 + c4 * 4];
        float4 bb = *(const float4*)(bias + bn + c4 * 4);
        v.x += bb.x; v.y += bb.y; v.z += bb.z; v.w += bb.w;
        *(float4*)(g_qkv + (size_t)(bm + m) * THREE_E + bn + c4 * 4) = v;
    }
}

// ============================================================
// Kernel 2: fused attention (byte-identical to R11).
// ============================================================
#define SSTR2 1034
#define QSTR  68
#define KSTR  68
#define VSTR  68
#define SS_BYTES  (32 * SSTR2 * 2)
#define K_BYTES   (128 * KSTR * 4)
#define ATTN_SMEM (SS_BYTES + K_BYTES + 128 + 32 * QSTR * 4)   // 109824

__global__ __launch_bounds__(256, 2)
void attn_kernel(float* __restrict__ out){
    extern __shared__ char smraw[];
    __half* Ss  = (__half*)smraw;
    float* Ks   = (float*)(smraw + SS_BYTES);
    float* rinv = (float*)(smraw + SS_BYTES + K_BYTES);
    float* Qs   = rinv + 32;
    float* Vs0  = Ks;
    float* Vs1  = Ks + 64 * VSTR;

    const int tid  = threadIdx.x;
    const int warp = tid >> 5;
    const int lane = tid & 31;
    const int bh   = blockIdx.x >> 5;
    const int row0 = (blockIdx.x & 31) * 32;
    const int b = bh / HEADS;
    const int h = bh % HEADS;

    const float* qbase = g_qkv + (size_t)(b * SEQ) * THREE_E + h * HDIM;
    const float* kbase = qbase + EMBED;
    const float* vbase = qbase + 2 * EMBED;

    #pragma unroll
    for (int it = 0; it < 2; it++){
        int idx = it * 256 + tid;
        int dc = idx & 15, r = idx >> 4;
        float4 v = *(const float4*)(qbase + (size_t)(row0 + r) * THREE_E + dc * 4);
        *(float4*)&Qs[r * QSTR + dc * 4] = v;
    }
    __syncthreads();

    const int r0 = warp * 4;

    #pragma unroll 1
    for (int kt = 0; kt < SEQ / 128; kt++){
        if (kt) __syncthreads();
        #pragma unroll
        for (int it = 0; it < 8; it++){
            int idx = it * 256 + tid;
            int m = idx >> 4, dc = idx & 15;
            float4 v = *(const float4*)(kbase + (size_t)(kt * 128 + m) * THREE_E + dc * 4);
            *(float4*)&Ks[m * KSTR + dc * 4] = v;
        }
        __syncthreads();

        unsigned long long acc[4][4];
        #pragma unroll
        for (int r = 0; r < 4; r++)
            #pragma unroll
            for (int i = 0; i < 4; i++) acc[r][i] = 0ull;

        #pragma unroll
        for (int dg = 0; dg < 16; dg++){
            ulonglong2 q[4];
            #pragma unroll
            for (int r = 0; r < 4; r++)
                q[r] = *(const ulonglong2*)&Qs[(r0 + r) * QSTR + dg * 4];
            #pragma unroll
            for (int i = 0; i < 4; i++){
                ulonglong2 kv = *(const ulonglong2*)&Ks[(lane + 32 * i) * KSTR + dg * 4];
                #pragma unroll
                for (int r = 0; r < 4; r++){
                    fma2(acc[r][i], q[r].x, kv.x);
                    fma2(acc[r][i], q[r].y, kv.y);
                }
            }
        }

        #pragma unroll
        for (int r = 0; r < 4; r++){
            __half* srow = Ss + (r0 + r) * SSTR2 + kt * 128 + lane;
            #pragma unroll
            for (int i = 0; i < 4; i++){
                float2 t = up2(acc[r][i]);
                srow[32 * i] = __float2half_rn(floorf((t.x + t.y) * 0.125f));
            }
        }
    }
    __syncthreads();

    float4 vp[4];
    #pragma unroll
    for (int it = 0; it < 4; it++){
        int idx = it * 256 + tid;
        int m = idx >> 4, dc = idx & 15;
        vp[it] = *(const float4*)(vbase + (size_t)m * THREE_E + dc * 4);
    }

    #pragma unroll
    for (int rr = 0; rr < 4; rr++){
        int r = warp * 4 + rr;
        __half2* row2 = (__half2*)(Ss + r * SSTR2);
        float mx = -1e30f;
        #pragma unroll
        for (int i = 0; i < 16; i++){
            float2 f = __half22float2(row2[lane + i * 32]);
            mx = fmaxf(mx, fmaxf(f.x, f.y));
        }
        #pragma unroll
        for (int o = 16; o > 0; o >>= 1) mx = fmaxf(mx, __shfl_xor_sync(0xffffffffu, mx, o));
        float sum = 0.f;
        #pragma unroll
        for (int i = 0; i < 16; i++){
            float2 f = __half22float2(row2[lane + i * 32]);
            __half2 e2 = __floats2half2_rn(__expf(f.x - mx), __expf(f.y - mx));
            row2[lane + i * 32] = e2;
            float2 q = __half22float2(e2);
            sum += q.x + q.y;
        }
        #pragma unroll
        for (int o = 16; o > 0; o >>= 1) sum += __shfl_xor_sync(0xffffffffu, sum, o);
        if (lane == 0) rinv[r] = 1.0f / sum;
    }

    #pragma unroll
    for (int it = 0; it < 4; it++){
        int idx = it * 256 + tid;
        int m = idx >> 4, dc = idx & 15;
        float4 v = vp[it];
        v.x = tf32r(v.x); v.y = tf32r(v.y); v.z = tf32r(v.z); v.w = tf32r(v.w);
        *(float4*)&Vs0[m * VSTR + dc * 4] = v;
    }
    #pragma unroll
    for (int it = 0; it < 4; it++){
        int idx = it * 256 + tid;
        int m = idx >> 4, dc = idx & 15;
        vp[it] = *(const float4*)(vbase + (size_t)(64 + m) * THREE_E + dc * 4);
    }
    __syncthreads();

    const int mtile = warp & 1;
    const int nt0   = (warp >> 1) * 2;
    float C0[4] = {0.f,0.f,0.f,0.f}, C1[4] = {0.f,0.f,0.f,0.f};

    const __half* eA0 = Ss + (mtile * 16 + (lane >> 2)) * SSTR2 + (lane & 3);
    const __half* eA1 = eA0 + 8 * SSTR2;
    const int bm_ = lane & 3;
    const int bd_ = lane >> 2;
    const int v_off = bm_ * VSTR + nt0 * 8 + bd_;

    #pragma unroll 1
    for (int kt = 0; kt < 16; kt++){
        const float* cur = (kt & 1) ? Vs1 : Vs0;
        const float* vs_b0 = cur + v_off;

        #pragma unroll
        for (int ks = 0; ks < 8; ks++){
            const int eo = kt * 64 + ks * 8;
            uint32_t ea[4];
            ea[0] = __float_as_uint(__half2float(eA0[eo]));
            ea[1] = __float_as_uint(__half2float(eA1[eo]));
            ea[2] = __float_as_uint(__half2float(eA0[eo + 4]));
            ea[3] = __float_as_uint(__half2float(eA1[eo + 4]));
            const float* vrow0 = vs_b0 + (8 * ks) * VSTR;
            const float* vrow1 = vrow0 + 4 * VSTR;
            uint32_t b0[2], b1[2];
            b0[0] = __float_as_uint(vrow0[0]);
            b0[1] = __float_as_uint(vrow1[0]);
            b1[0] = __float_as_uint(vrow0[8]);
            b1[1] = __float_as_uint(vrow1[8]);
            mma_tf32(C0, ea, b0);
            mma_tf32(C1, ea, b1);
        }

        if (kt < 15){
            float* nxt = (kt & 1) ? Vs0 : Vs1;
            #pragma unroll
            for (int it = 0; it < 4; it++){
                int idx = it * 256 + tid;
                int m = idx >> 4, dc = idx & 15;
                float4 v = vp[it];
                v.x = tf32r(v.x); v.y = tf32r(v.y); v.z = tf32r(v.z); v.w = tf32r(v.w);
                *(float4*)&nxt[m * VSTR + dc * 4] = v;
            }
            if (kt < 14){
                #pragma unroll
                for (int it = 0; it < 4; it++){
                    int idx = it * 256 + tid;
                    int m = idx >> 4, dc = idx & 15;
                    vp[it] = *(const float4*)(vbase + (size_t)((kt + 2) * 64 + m) * THREE_E + dc * 4);
                }
            }
        }
        __syncthreads();
    }

    {
        const int er0 = mtile * 16 + (lane >> 2);
        const int d0  = nt0 * 8 + 2 * (lane & 3);
        float i0 = rinv[er0], i1 = rinv[er0 + 8];
        float* op0 = out + (size_t)(bh * SEQ + row0 + er0) * HDIM + d0;
        float* op1 = op0 + 8 * HDIM;
        *(float2*)op0       = make_float2(C0[0] * i0, C0[1] * i0);
        *(float2*)(op0 + 8) = make_float2(C1[0] * i0, C1[1] * i0);
        *(float2*)op1       = make_float2(C0[2] * i1, C0[3] * i1);
        *(float2*)(op1 + 8) = make_float2(C1[2] * i1, C1[3] * i1);
    }
}

// ============================================================
// launch: scalar Q/K GEMM (s0) || tf32 V GEMM (s2), join, attn (s0).
// Capture-legal fork/join via events; statics created pre-capture.
// ============================================================
extern "C" void kernel_launch(void* const* d_in, const int* in_sizes, int n_in,
                              void* d_out, int out_size) {
    const float* x    = (const float*)d_in[0];   // [8,1024,768]
    const float* Wqkv = (const float*)d_in[1];   // [2304,768]
    const float* bqkv = (const float*)d_in[2];   // [2304]
    float* out = (float*)d_out;                  // [8,12,1024,64]

    static cudaStream_t s2 = nullptr;
    static cudaEvent_t evF = nullptr, evV = nullptr;
    if (s2 == nullptr){
        cudaStreamCreateWithFlags(&s2, cudaStreamNonBlocking);
        cudaEventCreateWithFlags(&evF, cudaEventDisableTiming);
        cudaEventCreateWithFlags(&evV, cudaEventDisableTiming);
        cudaFuncSetAttribute(attn_kernel, cudaFuncAttributeMaxDynamicSharedMemorySize, ATTN_SMEM);
        cudaFuncSetAttribute(qkv_gemm_v, cudaFuncAttributeMaxDynamicSharedMemorySize, VGEMM_SMEM);
    }

    // fork s2 from the capture-origin stream
    cudaEventRecord(evF, 0);
    cudaStreamWaitEvent(s2, evF, 0);

    // V columns via tensor cores (s2) — independent of scalar Q/K GEMM
    qkv_gemm_v<<<dim3(6, 64), 256, VGEMM_SMEM, s2>>>(x, Wqkv, bqkv);

    // Q/K columns, exact fp32 (s0)
    qkv_gemm<<<dim3(12, 64), 256>>>(x, Wqkv, bqkv);

    // join V GEMM back before attention
    cudaEventRecord(evV, s2);
    cudaStreamWaitEvent(0, evV, 0);

    attn_kernel<<<BATCH * HEADS * (SEQ / 32), 256, ATTN_SMEM>>>(out);
}